// round 7
// baseline (speedup 1.0000x reference)
#include <cuda_runtime.h>
#include <cuda_fp16.h>

#define H_IMG 1080
#define W_IMG 1920
#define GY 16
#define GX 16
#define GW 8
#define NPIX (H_IMG * W_IMG)

#define BX 256                  // threads per block
#define PXT 2                   // pixels per thread, strided by BX
#define STRIP (BX * PXT)        // 512 pixels per strip
#define NC 6                    // x-cells covered by one strip
#define NCELL (NC * GW)         // 48 cells

#define SX (15.0f / 1919.0f)
#define SY (15.0f / 1079.0f)

__device__ __forceinline__ float2 h2f(unsigned u) {
    __half2 h;
    *reinterpret_cast<unsigned*>(&h) = u;
    return __half22float2(h);
}
__device__ __forceinline__ unsigned f2h2(float a, float b) {
    __half2 h = __floats2half2_rn(a, b);
    return *reinterpret_cast<unsigned*>(&h);
}

__global__ __launch_bounds__(BX) void bilateral_grid_kernel(
    const float* __restrict__ rgb,
    const float* __restrict__ grids,
    const int*   __restrict__ idxp,
    float*       __restrict__ out)
{
    // per cell: val[12] fp16 (24B) then dz[12] fp16 (24B) = 48B, 16B-aligned
    __shared__ __align__(16) unsigned slab[NCELL * 12];   // 48 cells * 48B = 2304B

    const int tid   = threadIdx.x;
    const int row   = blockIdx.y;
    const int xpix0 = blockIdx.x * STRIP;

    // ---- prefetch rgb early (lane-adjacent -> coalesced) ----
    const int x0p = xpix0 + tid;
    const int nA  = row * W_IMG + x0p;
    const int nB  = nA + BX;
    bool hasB = (x0p + BX < W_IMG);

    float rA = __ldcs(rgb + nA);
    float gA = __ldcs(rgb + NPIX + nA);
    float bA = __ldcs(rgb + 2 * NPIX + nA);
    float rB = 0.f, gB = 0.f, bB = 0.f;
    if (hasB) {
        rB = __ldcs(rgb + nB);
        gB = __ldcs(rgb + NPIX + nB);
        bB = __ldcs(rgb + 2 * NPIX + nB);
    }

    // ---- block-uniform y lerp ----
    float gyv = (float)row * SY;
    float fy  = floorf(gyv);
    float wy  = gyv - fy;
    int y0 = min((int)fy, GY - 1);
    int y1 = min(y0 + 1, GY - 1);
    float wy0 = 1.0f - wy, wy1 = wy;

    const float* grid = grids + (size_t)idxp[0] * (GY * GX * GW * 12);
    int xbase = (int)((float)xpix0 * SX);

    // ---- build slab: 144 items = (cell 0..47, chunk4 0..2) ----
    if (tid < NCELL * 3) {
        int cell = tid / 3;
        int c4   = tid - cell * 3;
        int xq   = cell / GW;
        int zq   = cell - xq * GW;
        int zq1  = min(zq + 1, GW - 1);
        int xc   = min(xbase + xq, GX - 1);

        const float4* p00 = reinterpret_cast<const float4*>(
            grid + ((size_t)(y0 * GX + xc) * GW + zq)  * 12) + c4;
        const float4* p10 = reinterpret_cast<const float4*>(
            grid + ((size_t)(y1 * GX + xc) * GW + zq)  * 12) + c4;
        const float4* p01 = reinterpret_cast<const float4*>(
            grid + ((size_t)(y0 * GX + xc) * GW + zq1) * 12) + c4;
        const float4* p11 = reinterpret_cast<const float4*>(
            grid + ((size_t)(y1 * GX + xc) * GW + zq1) * 12) + c4;
        float4 a0 = __ldg(p00);
        float4 a1 = __ldg(p10);
        float4 b0 = __ldg(p01);
        float4 b1 = __ldg(p11);
        float4 v, nx;
        v.x  = wy0 * a0.x + wy1 * a1.x;  v.y  = wy0 * a0.y + wy1 * a1.y;
        v.z  = wy0 * a0.z + wy1 * a1.z;  v.w  = wy0 * a0.w + wy1 * a1.w;
        nx.x = wy0 * b0.x + wy1 * b1.x;  nx.y = wy0 * b0.y + wy1 * b1.y;
        nx.z = wy0 * b0.z + wy1 * b1.z;  nx.w = wy0 * b0.w + wy1 * b1.w;

        unsigned* cb = slab + cell * 12;          // 12 uint (48B) per cell
        cb[c4 * 2 + 0] = f2h2(v.x, v.y);          // val halves [c4*4 .. ]
        cb[c4 * 2 + 1] = f2h2(v.z, v.w);
        cb[6 + c4 * 2 + 0] = f2h2(nx.x - v.x, nx.y - v.y);   // dz halves
        cb[6 + c4 * 2 + 1] = f2h2(nx.z - v.z, nx.w - v.w);
    }
    __syncthreads();

    const uint4* S = reinterpret_cast<const uint4*>(slab);   // cell = 3 uint4

    #pragma unroll
    for (int k = 0; k < PXT; k++) {
        if (k == 1 && !hasB) break;
        const int x = x0p + k * BX;
        const int n = row * W_IMG + x;

        float r = (k == 0) ? rA : rB;
        float g = (k == 0) ? gA : gB;
        float b = (k == 0) ? bA : bB;

        float gray = 0.299f * r + 0.587f * g + 0.114f * b;

        float gxv = (float)x * SX;
        float fx  = floorf(gxv);
        float wx  = gxv - fx;
        int xc0 = min((int)fx, GX - 1);
        int xc1 = min(xc0 + 1, GX - 1);
        int x0l = xc0 - xbase;
        int x1l = xc1 - xbase;

        float gz = __saturatef(gray) * (float)(GW - 1);
        float fz = floorf(gz);
        float wz = gz - fz;
        int z0 = min(max((int)fz, 0), GW - 1);

        float w0 = 1.0f - wx;
        float w1 = wx;

        int ia = (x0l * GW + z0) * 3;
        int ib = (x1l * GW + z0) * 3;

        // 6 LDS.128, issued up front
        uint4 qa0 = S[ia], qa1 = S[ia + 1], qa2 = S[ia + 2];
        uint4 qb0 = S[ib], qb1 = S[ib + 1], qb2 = S[ib + 2];

        // qa0: v0..v7 | qa1: v8..v11, d0..d3 | qa2: d4..d11
        float acc[12];

        #define PAIR(dst0, dst1, uv, ud, wcorn)                           \
        {                                                                  \
            float2 fv = h2f(uv);                                           \
            float2 fd = h2f(ud);                                           \
            dst0 += (wcorn) * (fv.x + wz * fd.x);                          \
            dst1 += (wcorn) * (fv.y + wz * fd.y);                          \
        }

        #pragma unroll
        for (int j = 0; j < 12; j++) acc[j] = 0.0f;

        // corner A (weight w0)
        PAIR(acc[0],  acc[1],  qa0.x, qa1.z, w0)
        PAIR(acc[2],  acc[3],  qa0.y, qa1.w, w0)
        PAIR(acc[4],  acc[5],  qa0.z, qa2.x, w0)
        PAIR(acc[6],  acc[7],  qa0.w, qa2.y, w0)
        PAIR(acc[8],  acc[9],  qa1.x, qa2.z, w0)
        PAIR(acc[10], acc[11], qa1.y, qa2.w, w0)
        // corner B (weight w1)
        PAIR(acc[0],  acc[1],  qb0.x, qb1.z, w1)
        PAIR(acc[2],  acc[3],  qb0.y, qb1.w, w1)
        PAIR(acc[4],  acc[5],  qb0.z, qb2.x, w1)
        PAIR(acc[6],  acc[7],  qb0.w, qb2.y, w1)
        PAIR(acc[8],  acc[9],  qb1.x, qb2.z, w1)
        PAIR(acc[10], acc[11], qb1.y, qb2.w, w1)
        #undef PAIR

        float4 a0 = make_float4(acc[0], acc[1], acc[2],  acc[3]);
        float4 a1 = make_float4(acc[4], acc[5], acc[6],  acc[7]);
        float4 a2 = make_float4(acc[8], acc[9], acc[10], acc[11]);

        float4* aout = reinterpret_cast<float4*>(out) + (size_t)n * 3;
        __stcs(aout + 0, a0);
        __stcs(aout + 1, a1);
        __stcs(aout + 2, a2);

        float* res = out + (size_t)12 * NPIX + (size_t)n * 3;
        __stcs(res + 0, a0.x * r + a0.y * g + a0.z * b + a0.w);
        __stcs(res + 1, a1.x * r + a1.y * g + a1.z * b + a1.w);
        __stcs(res + 2, a2.x * r + a2.y * g + a2.z * b + a2.w);
    }
}

extern "C" void kernel_launch(void* const* d_in, const int* in_sizes, int n_in,
                              void* d_out, int out_size) {
    const float* rgb   = (const float*)d_in[0];
    const float* grids = (const float*)d_in[1];
    const int*   idx   = (const int*)d_in[2];
    float* out = (float*)d_out;

    dim3 grid((W_IMG + STRIP - 1) / STRIP, H_IMG);   // 4 x 1080
    bilateral_grid_kernel<<<grid, BX>>>(rgb, grids, idx, out);
}